// round 13
// baseline (speedup 1.0000x reference)
#include <cuda_runtime.h>
#include <cuda_bf16.h>
#include <cstdint>

#define BB   2
#define NN   2048
#define NTT  8
#define DZC  16
#define GG   (NTT*64*64)
#define XG_SZ (BB*GG*3)           // 196608
#define ZG_SZ (BB*GG*DZC)         // 1048576
#define LOG2E 1.4426950408889634f

// ---- global scratch ----
__device__ float   g_ww[BB*64*NN];    // [b][w][n]  w-direction factor (coord 2)
__device__ float   g_sh[BB*64*NN];    // [b][h][n]  h-direction factor (coord 1)
// A fragment planes: [b][h][rb(4)][ks(128)][lane(32)][16B]  (bf16x2 a0..a3)
__device__ uint8_t g_Ahi[(size_t)BB*64*4*128*32*16];   // 32 MB
__device__ uint8_t g_Alo[(size_t)BB*64*4*128*32*16];   // 32 MB
// B fragments: [b][cb(16)][ks(128)][lane(32)][16B: b0hi b1hi b0lo b1lo]
__device__ uint8_t g_Bt[(size_t)BB*16*128*32*16];      // 2 MB

// ---------- helpers ----------
__device__ __forceinline__ float ex2(float x) {
    float y; asm("ex2.approx.ftz.f32 %0, %1;" : "=f"(y) : "f"(x)); return y;
}
__device__ __forceinline__ float inv_ls(const float* lsp, int d) {
    float p = lsp[d];
    return 1.0f / (1e-5f + log1pf(__expf(p)));
}
__device__ __forceinline__ uint32_t smem_u32(const void* p) {
    uint32_t a;
    asm("{ .reg .u64 t; cvta.to.shared.u64 t, %1; cvt.u32.u64 %0, t; }" : "=r"(a) : "l"(p));
    return a;
}
__device__ __forceinline__ void cp_async16(uint32_t dst, const void* src) {
    asm volatile("cp.async.cg.shared.global [%0], [%1], 16;" :: "r"(dst), "l"(src));
}
__device__ __forceinline__ void cp_commit() { asm volatile("cp.async.commit_group;" ::: "memory"); }

__device__ __forceinline__ uint32_t cvt_bf2(float hi, float lo) {
    uint32_t r; asm("cvt.rn.bf16x2.f32 %0, %1, %2;" : "=r"(r) : "f"(hi), "f"(lo)); return r;
}
// split pair (f0 -> low half = lower k, f1 -> high half) into bf16 hi + residual lo
__device__ __forceinline__ void split2(float f0, float f1, uint32_t& hi, uint32_t& lo) {
    hi = cvt_bf2(f1, f0);
    float h0 = __uint_as_float(hi << 16);
    float h1 = __uint_as_float(hi & 0xffff0000u);
    lo = cvt_bf2(f1 - h1, f0 - h0);
}
__device__ __forceinline__ void mma16816(float* c, uint32_t a0, uint32_t a1,
                                         uint32_t a2, uint32_t a3,
                                         uint32_t b0, uint32_t b1) {
    asm volatile(
        "mma.sync.aligned.m16n8k16.row.col.f32.bf16.bf16.f32 "
        "{%0,%1,%2,%3}, {%4,%5,%6,%7}, {%8,%9}, {%0,%1,%2,%3};"
        : "+f"(c[0]), "+f"(c[1]), "+f"(c[2]), "+f"(c[3])
        : "r"(a0), "r"(a1), "r"(a2), "r"(a3), "r"(b0), "r"(b1));
}

// ---------- P0: xgrid + base factor tables ----------
#define P0_N (XG_SZ + 2 * BB * 64 * NN)    // 720896

__global__ void p0_kernel(const float* __restrict__ x, const float* __restrict__ tg,
                          const float* __restrict__ lsp, float* __restrict__ xg) {
    int idx = blockIdx.x * blockDim.x + threadIdx.x;
    if (idx < XG_SZ) {
        if (xg) {
            int d = idx % 3;
            int p = idx / 3;
            int w = p & 63; p >>= 6;
            int h = p & 63; p >>= 6;
            int t = p & 7;
            int b = p >> 3;
            float v;
            if (d == 0)      v = tg[b * NTT + t];
            else if (d == 1) v = -1.0f + (2.0f / 63.0f) * (float)h;
            else             v = -1.0f + (2.0f / 63.0f) * (float)w;
            xg[idx] = v;
        }
        return;
    }
    idx -= XG_SZ;
    if (idx >= 2 * BB * 64 * NN) return;
    int n   = idx & (NN - 1);
    int r   = (idx >> 11) & 63;
    int b   = (idx >> 17) & 1;
    int tab = idx >> 18;
    int dim = tab ? 1 : 2;                  // tab0 = ww (coord 2), tab1 = sh (coord 1)
    float inv = inv_ls(lsp, dim);
    float c   = x[(b * NN + n) * 3 + dim] * inv;
    float gv  = (-1.0f + (2.0f / 63.0f) * (float)r) * inv;
    float d   = gv - c;
    float e   = ex2(-0.5f * LOG2E * d * d);
    (tab ? g_sh : g_ww)[(b * 64 + r) * NN + n] = e;
}

// ---------- PA: A fragments (weights pre-split bf16 hi/lo) ----------
// thread -> (b, h, rb, ks, lane); writes one uint4 per plane
__global__ __launch_bounds__(256)
void pa_kernel() {
    int idx = blockIdx.x * blockDim.x + threadIdx.x;   // 2*64*4*128*32 = 2097152
    int lane = idx & 31;
    int ks   = (idx >> 5) & 127;
    int rb   = (idx >> 12) & 3;
    int h    = (idx >> 14) & 63;
    int b    = idx >> 20;
    int lr = lane >> 2, q2 = (lane & 3) * 2;
    int w0 = rb * 16 + lr, w1 = w0 + 8;
    int n0 = ks * 16;

    const float* wwr0 = g_ww + (b * 64 + w0) * NN + n0;
    const float* wwr1 = g_ww + (b * 64 + w1) * NN + n0;
    const float* shr  = g_sh + (b * 64 + h) * NN + n0;

    float2 sA = *(const float2*)(shr + q2);       // k = q2, q2+1
    float2 sB = *(const float2*)(shr + q2 + 8);   // k = q2+8, q2+9
    float2 wa = *(const float2*)(wwr0 + q2);
    float2 wb = *(const float2*)(wwr1 + q2);
    float2 wc = *(const float2*)(wwr0 + q2 + 8);
    float2 wd = *(const float2*)(wwr1 + q2 + 8);

    uint32_t hi[4], lo[4];
    split2(wa.x * sA.x, wa.y * sA.y, hi[0], lo[0]);   // a0: row w0, k lo
    split2(wb.x * sA.x, wb.y * sA.y, hi[1], lo[1]);   // a1: row w1, k lo
    split2(wc.x * sB.x, wc.y * sB.y, hi[2], lo[2]);   // a2: row w0, k hi
    split2(wd.x * sB.x, wd.y * sB.y, hi[3], lo[3]);   // a3: row w1, k hi

    size_t off = ((((size_t)(b * 64 + h) * 4 + rb) * 128 + ks) * 32 + lane) * 16;
    *(uint4*)(g_Ahi + off) = make_uint4(hi[0], hi[1], hi[2], hi[3]);
    *(uint4*)(g_Alo + off) = make_uint4(lo[0], lo[1], lo[2], lo[3]);
}

// ---------- PB: B fragments (z_t pre-split bf16 hi/lo) ----------
__global__ __launch_bounds__(256)
void pb_kernel(const float* __restrict__ x, const float* __restrict__ z,
               const float* __restrict__ tg, const float* __restrict__ lsp) {
    int idx = blockIdx.x * blockDim.x + threadIdx.x;   // 2*16*128*32 = 131072
    int lane = idx & 31;
    int ks   = (idx >> 5) & 127;
    int cb   = (idx >> 12) & 15;
    int b    = idx >> 16;
    int lr = lane >> 2, q2 = (lane & 3) * 2;
    int col = cb * 8 + lr;
    int t = col >> 4, e = col & 15;
    int n0 = ks * 16;

    float inv0 = inv_ls(lsp, 0);
    float tv = tg[b * NTT + t] * inv0;

    float v[4];
    int nn[4] = {n0 + q2, n0 + q2 + 1, n0 + q2 + 8, n0 + q2 + 9};
#pragma unroll
    for (int j = 0; j < 4; j++) {
        int n = nn[j];
        float c0 = x[(b * NN + n) * 3 + 0] * inv0;
        float d  = tv - c0;
        float st = ex2(-0.5f * LOG2E * d * d);
        v[j] = st * z[(b * NN + n) * DZC + e];
    }
    uint32_t b0h, b0l, b1h, b1l;
    split2(v[0], v[1], b0h, b0l);
    split2(v[2], v[3], b1h, b1l);
    size_t off = (((size_t)(b * 16 + cb) * 128 + ks) * 32 + lane) * 16;
    *(uint4*)(g_Bt + off) = make_uint4(b0h, b1h, b0l, b1l);
}

// ---------- main HMMA kernel ----------
// CTA = (b, h): D[64 w-rows x 128 (t,e)-cols] = A[64,2048] x B[128,2048]^T.
// 8 warps = 2 row-groups x 4 col-groups, warp D[32x32].
#define KC     128
#define NCH    (NN / KC)       // 16
#define A_O    0               // 32 KB: [comp2][rb4][ksl8][lane32][16B]
#define B_O    32768           // 64 KB: [cb16][ksl8][lane32][16B]
#define BUFSZ  98304
#define SMEM_T (2 * BUFSZ)     // 196608

__global__ __launch_bounds__(256, 1)
void zgrid_mma_kernel(float* __restrict__ out) {
    extern __shared__ char smem[];
    const uint32_t sb = smem_u32(smem);
    const int tid  = threadIdx.x;
    const int wid  = tid >> 5;
    const int lane = tid & 31;

    const int b = blockIdx.x >> 6;
    const int h = blockIdx.x & 63;
    const int rw = wid & 1;             // row-group
    const int cw = wid >> 1;            // col-group
    const int lr = lane >> 2, q2 = (lane & 3) * 2;

    const size_t tileA = (size_t)(b * 64 + h) * 262144;   // 4*128*32*16

    float acc[2][4][4];
#pragma unroll
    for (int i = 0; i < 2; i++)
#pragma unroll
        for (int j = 0; j < 4; j++)
#pragma unroll
            for (int k = 0; k < 4; k++) acc[i][j][k] = 0.0f;

    auto stage = [&](int ch) {
        const uint32_t ba = sb + (ch & 1) * BUFSZ;
        // A: 2 comps x 4 rb x 8 ksl x 32 lanes = 2048 x 16B
        for (int i = tid; i < 2048; i += 256) {
            int comp = i >> 10;
            int r    = i & 1023;
            int rb   = r >> 8;
            int ksl  = (r >> 5) & 7;
            int ln   = i & 31;
            const uint8_t* src = (comp ? g_Alo : g_Ahi) + tileA
                               + ((size_t)(rb * 128 + ch * 8 + ksl) * 32 + ln) * 16;
            uint32_t dst = ba + A_O + comp * 16384 + ((rb * 8 + ksl) * 32 + ln) * 16;
            cp_async16(dst, src);
        }
        // B: 16 cb x 8 ksl x 32 lanes = 4096 x 16B
        for (int i = tid; i < 4096; i += 256) {
            int cb  = i >> 8;
            int ksl = (i >> 5) & 7;
            int ln  = i & 31;
            const uint8_t* src = g_Bt
                + (((size_t)(b * 16 + cb) * 128 + ch * 8 + ksl) * 32 + ln) * 16;
            uint32_t dst = ba + B_O + (cb * 8 + ksl) * 512 + ln * 16;
            cp_async16(dst, src);
        }
        cp_commit();
    };

    stage(0);

    for (int ch = 0; ch < NCH; ch++) {
        if (ch + 1 < NCH) {
            stage(ch + 1);
            asm volatile("cp.async.wait_group 1;" ::: "memory");
        } else {
            asm volatile("cp.async.wait_group 0;" ::: "memory");
        }
        __syncthreads();

        const char* buf = smem + (ch & 1) * BUFSZ;

#pragma unroll
        for (int ksl = 0; ksl < 8; ksl++) {
            uint4 ah0 = *(const uint4*)(buf + A_O + (((rw * 2 + 0) * 8 + ksl) * 32 + lane) * 16);
            uint4 ah1 = *(const uint4*)(buf + A_O + (((rw * 2 + 1) * 8 + ksl) * 32 + lane) * 16);
            uint4 al0 = *(const uint4*)(buf + A_O + 16384 + (((rw * 2 + 0) * 8 + ksl) * 32 + lane) * 16);
            uint4 al1 = *(const uint4*)(buf + A_O + 16384 + (((rw * 2 + 1) * 8 + ksl) * 32 + lane) * 16);

#pragma unroll
            for (int cbl = 0; cbl < 4; cbl++) {
                int cb = cw * 4 + cbl;
                uint4 bb = *(const uint4*)(buf + B_O + (cb * 8 + ksl) * 512 + lane * 16);
                mma16816(acc[0][cbl], ah0.x, ah0.y, ah0.z, ah0.w, bb.x, bb.y);
                mma16816(acc[0][cbl], ah0.x, ah0.y, ah0.z, ah0.w, bb.z, bb.w);
                mma16816(acc[0][cbl], al0.x, al0.y, al0.z, al0.w, bb.x, bb.y);
                mma16816(acc[1][cbl], ah1.x, ah1.y, ah1.z, ah1.w, bb.x, bb.y);
                mma16816(acc[1][cbl], ah1.x, ah1.y, ah1.z, ah1.w, bb.z, bb.w);
                mma16816(acc[1][cbl], al1.x, al1.y, al1.z, al1.w, bb.x, bb.y);
            }
        }
        __syncthreads();
    }

    // ---- epilogue ----
#pragma unroll
    for (int rbl = 0; rbl < 2; rbl++) {
#pragma unroll
        for (int cbl = 0; cbl < 4; cbl++) {
            int w0   = rw * 32 + rbl * 16 + lr;      // 0..63
            int col0 = (cw * 4 + cbl) * 8 + q2;      // 0..127
            int t = col0 >> 4, e = col0 & 15;
            size_t i0 = (((size_t)(b * NTT + t) * 64 + h) * 64 + w0) * DZC + e;
            *(float2*)(out + i0) = make_float2(acc[rbl][cbl][0], acc[rbl][cbl][1]);
            size_t i1 = i0 + 8 * DZC;                // row w0+8
            *(float2*)(out + i1) = make_float2(acc[rbl][cbl][2], acc[rbl][cbl][3]);
        }
    }
}

extern "C" void kernel_launch(void* const* d_in, const int* in_sizes, int n_in,
                              void* d_out, int out_size) {
    const float* x   = (const float*)d_in[0];
    const float* z   = (const float*)d_in[1];
    const float* tg  = (const float*)d_in[2];
    const float* lsp = (const float*)d_in[3];
    float* out = (float*)d_out;

    float* xg = nullptr;
    float* zg = nullptr;
    if (out_size == XG_SZ + ZG_SZ)      { xg = out; zg = out + XG_SZ; }
    else if (out_size == ZG_SZ)         { zg = out; }
    else if (out_size == XG_SZ)         { xg = out; }
    else                                { xg = out; zg = out + XG_SZ; }

    p0_kernel<<<(P0_N + 255) / 256, 256>>>(x, tg, lsp, xg);
    if (zg) {
        cudaFuncSetAttribute(zgrid_mma_kernel,
                             cudaFuncAttributeMaxDynamicSharedMemorySize, SMEM_T);
        pa_kernel<<<8192, 256>>>();
        pb_kernel<<<512, 256>>>(x, z, tg, lsp);
        zgrid_mma_kernel<<<BB * 64, 256, SMEM_T>>>(zg);
    }
}